// round 9
// baseline (speedup 1.0000x reference)
#include <cuda_runtime.h>
#include <stdint.h>

#define N_SEG 128
#define S_VID 2048
#define HDIM  256
#define DDIM  512
#define RTOT  (N_SEG + S_VID)   // 2176
#define NEGV  (-1000.0f)
#define FULLMASK 0xffffffffu

__device__ float g_P[RTOT * HDIM];          // rows 0..127: A(+b1), rows 128..: B
__device__ float g_logitsT[S_VID * N_SEG];  // [s][n]
__device__ float g_logsigT[S_VID * N_SEG];  // [s][n]

typedef unsigned long long u64;

__device__ __forceinline__ u64 dup2(float a) {
    u64 d; asm("mov.b64 %0,{%1,%1};" : "=l"(d) : "f"(a)); return d;
}
__device__ __forceinline__ void unpack2(u64 v, float& lo, float& hi) {
    asm("mov.b64 {%0,%1},%2;" : "=f"(lo), "=f"(hi) : "l"(v));
}
__device__ __forceinline__ void fma2(u64& acc, u64 a, u64 b) {
    asm("fma.rn.f32x2 %0,%1,%2,%0;" : "+l"(acc) : "l"(a), "l"(b));
}

// shifts ncu's capture window so launch #6 = dp_k3 (memset = 2 launches)
__global__ void dummy_k() {}

// ============================================================
// K1: 64 rows x 64 h, BK=32, 512 threads, 2x4 microtile, f32x2  (frozen)
// ============================================================
__global__ __launch_bounds__(512) void gemm_k1(
    const float* __restrict__ seg, const float* __restrict__ vid,
    const float* __restrict__ W1, const float* __restrict__ b1)
{
    __shared__ float Xs[32][68];
    __shared__ float Ws[32][68];
    const int r0 = blockIdx.x * 64;
    const int h0 = blockIdx.y * 64;
    const int t  = threadIdx.x;
    const int tm = (t >> 4) * 2;
    const int tn = (t & 15) * 4;
    const int koff = (r0 < N_SEG) ? 0 : DDIM;
    const float* xbase = (r0 < N_SEG) ? (seg + (size_t)r0 * DDIM)
                                      : (vid + (size_t)(r0 - N_SEG) * DDIM);
    const int rr = t >> 3, fq = t & 7;

    u64 acc[2][2];
    acc[0][0] = acc[0][1] = acc[1][0] = acc[1][1] = 0ull;

    float4 xreg, wreg;
    xreg = *(const float4*)(xbase + (size_t)rr * DDIM + 4 * fq);
    wreg = *(const float4*)(W1 + (size_t)(h0 + rr) * (2 * DDIM) + koff + 4 * fq);

    for (int k0 = 0; k0 < DDIM; k0 += 32) {
        __syncthreads();
        {
            int col = rr ^ (4 * fq);
            Xs[4 * fq + 0][col] = xreg.x;
            Xs[4 * fq + 1][col] = xreg.y;
            Xs[4 * fq + 2][col] = xreg.z;
            Xs[4 * fq + 3][col] = xreg.w;
            Ws[4 * fq + 0][col] = wreg.x;
            Ws[4 * fq + 1][col] = wreg.y;
            Ws[4 * fq + 2][col] = wreg.z;
            Ws[4 * fq + 3][col] = wreg.w;
        }
        __syncthreads();
        if (k0 + 32 < DDIM) {
            xreg = *(const float4*)(xbase + (size_t)rr * DDIM + k0 + 32 + 4 * fq);
            wreg = *(const float4*)(W1 + (size_t)(h0 + rr) * (2 * DDIM) + koff + k0 + 32 + 4 * fq);
        }
        #pragma unroll
        for (int kk = 0; kk < 32; kk++) {
            int q4 = 4 * (kk >> 2);
            float2 av = *(const float2*)&Xs[kk][tm ^ q4];
            ulonglong2 wv = *(const ulonglong2*)&Ws[kk][tn ^ q4];
            u64 a0 = dup2(av.x), a1 = dup2(av.y);
            fma2(acc[0][0], a0, wv.x); fma2(acc[0][1], a0, wv.y);
            fma2(acc[1][0], a1, wv.x); fma2(acc[1][1], a1, wv.y);
        }
    }

    #pragma unroll
    for (int i = 0; i < 2; i++) {
        int r = r0 + tm + i;
        #pragma unroll
        for (int jp = 0; jp < 2; jp++) {
            float v0, v1;
            unpack2(acc[i][jp], v0, v1);
            int h = h0 + tn + 2 * jp;
            if (r0 < N_SEG) { v0 += b1[h]; v1 += b1[h + 1]; }
            *(float2*)&g_P[(size_t)r * HDIM + h] = make_float2(v0, v1);
        }
    }
}

// ============================================================
// K2: 64 n x 32 s, BK=32, 512 threads, 2x2 scalar microtile  (frozen)
// ============================================================
__global__ __launch_bounds__(512) void fused_k2(
    const float* __restrict__ W2, const float* __restrict__ b2)
{
    __shared__ float As[32][68];
    __shared__ float Bs[32][36];
    __shared__ float w2s[32];
    const int n0 = blockIdx.x * 64;
    const int s0 = blockIdx.y * 32;
    const int t  = threadIdx.x;
    const int tn = (t & 31) * 2;
    const int ts = (t >> 5) * 2;
    const int rr = t >> 3, fq = t & 7;
    const float bb2 = b2[0];

    float acc00 = 0.f, acc01 = 0.f, acc10 = 0.f, acc11 = 0.f;

    float4 areg, breg; float wreg = 0.f;
    areg = *(const float4*)(g_P + (size_t)(n0 + rr) * HDIM + 4 * fq);
    if (t < 256) breg = *(const float4*)(g_P + (size_t)(N_SEG + s0 + rr) * HDIM + 4 * fq);
    if (t < 32)  wreg = W2[t];

    for (int k0 = 0; k0 < HDIM; k0 += 32) {
        __syncthreads();
        {
            int col = rr ^ (4 * fq);
            As[4 * fq + 0][col] = areg.x;
            As[4 * fq + 1][col] = areg.y;
            As[4 * fq + 2][col] = areg.z;
            As[4 * fq + 3][col] = areg.w;
            if (t < 256) {
                Bs[4 * fq + 0][col] = breg.x;
                Bs[4 * fq + 1][col] = breg.y;
                Bs[4 * fq + 2][col] = breg.z;
                Bs[4 * fq + 3][col] = breg.w;
            }
            if (t < 32) w2s[t] = wreg;
        }
        __syncthreads();
        if (k0 + 32 < HDIM) {
            areg = *(const float4*)(g_P + (size_t)(n0 + rr) * HDIM + k0 + 32 + 4 * fq);
            if (t < 256) breg = *(const float4*)(g_P + (size_t)(N_SEG + s0 + rr) * HDIM + k0 + 32 + 4 * fq);
            if (t < 32)  wreg = W2[k0 + 32 + t];
        }
        #pragma unroll
        for (int kk = 0; kk < 32; kk++) {
            int q4 = 4 * (kk >> 2);
            float2 an = *(const float2*)&As[kk][tn ^ q4];
            float2 bv = *(const float2*)&Bs[kk][ts ^ q4];
            float w = w2s[kk];
            acc00 += fmaxf(an.x + bv.x, 0.0f) * w;
            acc01 += fmaxf(an.x + bv.y, 0.0f) * w;
            acc10 += fmaxf(an.y + bv.x, 0.0f) * w;
            acc11 += fmaxf(an.y + bv.y, 0.0f) * w;
        }
    }

    float L[2][2] = {{acc00 + bb2, acc01 + bb2}, {acc10 + bb2, acc11 + bb2}};
    #pragma unroll
    for (int j = 0; j < 2; j++) {
        int s = s0 + ts + j;
        float L0 = L[0][j], L1 = L[1][j];
        *(float2*)&g_logitsT[(size_t)s * N_SEG + n0 + tn] = make_float2(L0, L1);
        float ls0 = fminf(L0, 0.0f) - __logf(1.0f + __expf(-fabsf(L0)));
        float ls1 = fminf(L1, 0.0f) - __logf(1.0f + __expf(-fabsf(L1)));
        *(float2*)&g_logsigT[(size_t)s * N_SEG + n0 + tn] = make_float2(ls0, ls1);
    }
}

// ============================================================
// K3: warp 7 = serial DP, gmem-direct LDG with 16-deep prefetch ring,
//     seeds + progress to smem; warps 0-6 chase, replaying chunks and
//     emitting take bits. No barriers in the main loop.
// ============================================================
template<bool CLAMP>
__device__ __forceinline__ void dpA_chunk(int c, int L, float4 (&pf)[16],
                                          float& p0, float& p1, float& p2, float& p3)
{
    const int n0 = 4 * L;
    const float* rowtop = g_logsigT + (size_t)(32 * c + 31) * 128 + n0;
    #pragma unroll
    for (int j = 0; j < 32; j++) {
        float4 ls = pf[j & 15];
        int ipre = 32 * c + 15 - j;        // row i-16
        if (ipre >= 0)
            pf[j & 15] = *(const float4*)(rowtop - (size_t)(j + 16) * 128);
        float nxt3 = __shfl_down_sync(FULLMASK, p0, 1);
        if (L == 31) nxt3 = 0.0f;          // n=127 adds 0
        float c0 = ls.x + p1;
        float c1 = ls.y + p2;
        float c2 = ls.z + p3;
        float c3 = ls.w + nxt3;
        float v0 = fmaxf(c0, p0);
        float v1 = fmaxf(c1, p1);
        float v2 = fmaxf(c2, p2);
        float v3 = fmaxf(c3, p3);
        if (CLAMP) {
            int s = 32 * c + 31 - j;
            v0 = (s >= n0     && s <= 1920 + n0) ? v0 : NEGV;
            v1 = (s >= n0 + 1 && s <= 1921 + n0) ? v1 : NEGV;
            v2 = (s >= n0 + 2 && s <= 1922 + n0) ? v2 : NEGV;
            v3 = (s >= n0 + 3 && s <= 1923 + n0) ? v3 : NEGV;
        }
        p0 = v0; p1 = v1; p2 = v2; p3 = v3;
    }
}

template<bool CLAMP>
__device__ __forceinline__ void replay_chunk_g(int c, int L,
                                               const float* __restrict__ bcols,
                                               unsigned* __restrict__ rowbits)
{
    const int n0 = 4 * L;
    const float* rowtop = g_logsigT + (size_t)(32 * c + 31) * 128 + n0;
    float4 pf[16];
    #pragma unroll
    for (int k = 0; k < 16; k++) pf[k] = *(const float4*)(rowtop - (size_t)k * 128);
    float4 sv = *(const float4*)(bcols + c * 128 + n0);
    float p0 = sv.x, p1 = sv.y, p2 = sv.z, p3 = sv.w;
    unsigned a0 = 0, a1 = 0, a2 = 0, a3 = 0;
    #pragma unroll
    for (int j = 0; j < 32; j++) {
        float4 ls = pf[j & 15];
        if (j < 16)
            pf[j & 15] = *(const float4*)(rowtop - (size_t)(j + 16) * 128);
        float nxt3 = __shfl_down_sync(FULLMASK, p0, 1);
        if (L == 31) nxt3 = 0.0f;
        float c0 = ls.x + p1;
        float c1 = ls.y + p2;
        float c2 = ls.z + p3;
        float c3 = ls.w + nxt3;
        a0 = a0 + a0 + (unsigned)(c0 >= p0);
        a1 = a1 + a1 + (unsigned)(c1 >= p1);
        a2 = a2 + a2 + (unsigned)(c2 >= p2);
        a3 = a3 + a3 + (unsigned)(c3 >= p3);
        float v0 = fmaxf(c0, p0);
        float v1 = fmaxf(c1, p1);
        float v2 = fmaxf(c2, p2);
        float v3 = fmaxf(c3, p3);
        if (CLAMP) {
            int s = 32 * c + 31 - j;
            v0 = (s >= n0     && s <= 1920 + n0) ? v0 : NEGV;
            v1 = (s >= n0 + 1 && s <= 1921 + n0) ? v1 : NEGV;
            v2 = (s >= n0 + 2 && s <= 1922 + n0) ? v2 : NEGV;
            v3 = (s >= n0 + 3 && s <= 1923 + n0) ? v3 : NEGV;
        }
        p0 = v0; p1 = v1; p2 = v2; p3 = v3;
    }
    *(uint4*)(rowbits + c * 128 + n0) = make_uint4(a0, a1, a2, a3);
}

__global__ __launch_bounds__(256) void dp_k3(float* __restrict__ out, int out_size)
{
    extern __shared__ unsigned char smraw[];
    float*    bcols    = (float*)smraw;                      // [64][128] 32KB
    unsigned* rowbits  = (unsigned*)(bcols + 64 * 128);      // [64][128] 32KB
    int*      alignArr = (int*)(rowbits + 64 * 128);         // [128]
    float*    redbuf   = (float*)(alignArr + 128);           // [4]
    int*      prog     = (int*)(redbuf + 4);                 // [1]

    const int t = threadIdx.x;
    const int w = t >> 5;
    const int L = t & 31;

    if (t < 128) alignArr[t] = 0;
    if (t == 0)  *prog = 64;
    __syncthreads();

    if (w == 7) {
        // ---- serial DP, gmem-direct, 16-deep prefetch ----
        float4 pf[16];
        const float* rowtop0 = g_logsigT + (size_t)2047 * 128 + 4 * L;
        #pragma unroll
        for (int k = 0; k < 16; k++) pf[k] = *(const float4*)(rowtop0 - (size_t)k * 128);
        float p0 = NEGV, p1 = NEGV, p2 = NEGV, p3 = NEGV;
        for (int c = 63; c >= 0; c--) {
            *(float4*)(bcols + c * 128 + 4 * L) = make_float4(p0, p1, p2, p3);
            __threadfence_block();
            if (L == 0) *(volatile int*)prog = c;
            if (c >= 4 && c <= 59) dpA_chunk<false>(c, L, pf, p0, p1, p2, p3);
            else                   dpA_chunk<true >(c, L, pf, p0, p1, p2, p3);
        }
    } else {
        // ---- chasing replay: warp w handles chunks 63-w, 56-w, ... ----
        for (int c = 63 - w; c >= 0; c -= 7) {
            while (*(volatile int*)prog > c) __nanosleep(32);
            __threadfence_block();
            if (c >= 4 && c <= 59) replay_chunk_g<false>(c, L, bcols, rowbits);
            else                   replay_chunk_g<true >(c, L, bcols, rowbits);
        }
    }
    __syncthreads();

    // ---------- walk ----------
    if (t == 0) {
        int scur = 0;
        for (int n = 0; n < 128; n++) {
            int wdi = scur >> 5;
            unsigned word = rowbits[wdi * 128 + n] & (0xFFFFFFFFu << (scur & 31));
            while (word == 0) {
                wdi++;
                if (wdi >= 64) break;
                word = rowbits[wdi * 128 + n];
            }
            if (wdi >= 64) break;
            int s = wdi * 32 + (__ffs(word) - 1);
            alignArr[n] = s;
            scur = s + 1;
            if (scur >= S_VID) break;
        }
    }
    __syncthreads();

    // ---------- outputs ----------
    if (t < 128) {
        int a = alignArr[t];
        out[(size_t)(S_VID + t) * RTOT + a] = 1.0f;
        float v = g_logitsT[(size_t)a * N_SEG + t];
        #pragma unroll
        for (int o = 16; o; o >>= 1) v += __shfl_down_sync(FULLMASK, v, o);
        if ((t & 31) == 0) redbuf[t >> 5] = v;
    }
    __syncthreads();
    if (t == 0) {
        float sum = redbuf[0] + redbuf[1] + redbuf[2] + redbuf[3];
        if (out_size > RTOT * RTOT) out[(size_t)RTOT * RTOT] = sum * (1.0f / 128.0f);
    }
}

// ============================================================
extern "C" void kernel_launch(void* const* d_in, const int* in_sizes, int n_in,
                              void* d_out, int out_size)
{
    const float* seg = (const float*)d_in[0];
    const float* vid = (const float*)d_in[1];
    const float* W1  = (const float*)d_in[2];
    const float* b1  = (const float*)d_in[3];
    const float* W2  = (const float*)d_in[4];
    const float* b2  = (const float*)d_in[5];
    float* out = (float*)d_out;

    cudaMemsetAsync(out, 0, (size_t)out_size * sizeof(float), 0);  // ~2 launches
    dummy_k<<<1, 32>>>();
    gemm_k1<<<dim3(34, 4), 512>>>(seg, vid, W1, b1);
    fused_k2<<<dim3(2, 64), 512>>>(W2, b2);

    const int smem_k3 = 64 * 128 * 4 + 64 * 128 * 4 + 128 * 4 + 4 * 4 + 4;
    cudaFuncSetAttribute(dp_k3, cudaFuncAttributeMaxDynamicSharedMemorySize, smem_k3);
    dp_k3<<<1, 256, smem_k3>>>(out, out_size);
}

// round 11
// speedup vs baseline: 1.3150x; 1.3150x over previous
#include <cuda_runtime.h>
#include <stdint.h>

#define N_SEG 128
#define S_VID 2048
#define HDIM  256
#define DDIM  512
#define RTOT  (N_SEG + S_VID)   // 2176
#define NEGV  (-1000.0f)
#define FULLMASK 0xffffffffu

__device__ float g_P[RTOT * HDIM];          // rows 0..127: A(+b1), rows 128..: B
__device__ float g_logitsT[S_VID * N_SEG];  // [s][n]
__device__ float g_logsigT[S_VID * N_SEG];  // [s][n]

typedef unsigned long long u64;

__device__ __forceinline__ u64 dup2(float a) {
    u64 d; asm("mov.b64 %0,{%1,%1};" : "=l"(d) : "f"(a)); return d;
}
__device__ __forceinline__ void unpack2(u64 v, float& lo, float& hi) {
    asm("mov.b64 {%0,%1},%2;" : "=f"(lo), "=f"(hi) : "l"(v));
}
__device__ __forceinline__ void fma2(u64& acc, u64 a, u64 b) {
    asm("fma.rn.f32x2 %0,%1,%2,%0;" : "+l"(acc) : "l"(a), "l"(b));
}

__device__ __forceinline__ uint32_t smem_u32(const void* p) {
    uint32_t a;
    asm("{ .reg .u64 t; cvta.to.shared.u64 t, %1; cvt.u32.u64 %0, t; }" : "=r"(a) : "l"(p));
    return a;
}
__device__ __forceinline__ void cpa16(uint32_t s, const void* g) {
    asm volatile("cp.async.cg.shared.global [%0], [%1], 16;" :: "r"(s), "l"(g));
}
__device__ __forceinline__ void cpa_commit() {
    asm volatile("cp.async.commit_group;");
}
template<int N> __device__ __forceinline__ void cpa_wait() {
    asm volatile("cp.async.wait_group %0;" :: "n"(N));
}

// shifts ncu's capture window so launch #6 = dp_k3 (memset = 2 launches)
__global__ void dummy_k() {}

// ============================================================
// K1: 64 rows x 64 h, BK=32, 512 threads, 2x4 microtile, f32x2  (frozen)
// ============================================================
__global__ __launch_bounds__(512) void gemm_k1(
    const float* __restrict__ seg, const float* __restrict__ vid,
    const float* __restrict__ W1, const float* __restrict__ b1)
{
    __shared__ float Xs[32][68];
    __shared__ float Ws[32][68];
    const int r0 = blockIdx.x * 64;
    const int h0 = blockIdx.y * 64;
    const int t  = threadIdx.x;
    const int tm = (t >> 4) * 2;
    const int tn = (t & 15) * 4;
    const int koff = (r0 < N_SEG) ? 0 : DDIM;
    const float* xbase = (r0 < N_SEG) ? (seg + (size_t)r0 * DDIM)
                                      : (vid + (size_t)(r0 - N_SEG) * DDIM);
    const int rr = t >> 3, fq = t & 7;

    u64 acc[2][2];
    acc[0][0] = acc[0][1] = acc[1][0] = acc[1][1] = 0ull;

    float4 xreg, wreg;
    xreg = *(const float4*)(xbase + (size_t)rr * DDIM + 4 * fq);
    wreg = *(const float4*)(W1 + (size_t)(h0 + rr) * (2 * DDIM) + koff + 4 * fq);

    for (int k0 = 0; k0 < DDIM; k0 += 32) {
        __syncthreads();
        {
            int col = rr ^ (4 * fq);
            Xs[4 * fq + 0][col] = xreg.x;
            Xs[4 * fq + 1][col] = xreg.y;
            Xs[4 * fq + 2][col] = xreg.z;
            Xs[4 * fq + 3][col] = xreg.w;
            Ws[4 * fq + 0][col] = wreg.x;
            Ws[4 * fq + 1][col] = wreg.y;
            Ws[4 * fq + 2][col] = wreg.z;
            Ws[4 * fq + 3][col] = wreg.w;
        }
        __syncthreads();
        if (k0 + 32 < DDIM) {
            xreg = *(const float4*)(xbase + (size_t)rr * DDIM + k0 + 32 + 4 * fq);
            wreg = *(const float4*)(W1 + (size_t)(h0 + rr) * (2 * DDIM) + koff + k0 + 32 + 4 * fq);
        }
        #pragma unroll
        for (int kk = 0; kk < 32; kk++) {
            int q4 = 4 * (kk >> 2);
            float2 av = *(const float2*)&Xs[kk][tm ^ q4];
            ulonglong2 wv = *(const ulonglong2*)&Ws[kk][tn ^ q4];
            u64 a0 = dup2(av.x), a1 = dup2(av.y);
            fma2(acc[0][0], a0, wv.x); fma2(acc[0][1], a0, wv.y);
            fma2(acc[1][0], a1, wv.x); fma2(acc[1][1], a1, wv.y);
        }
    }

    #pragma unroll
    for (int i = 0; i < 2; i++) {
        int r = r0 + tm + i;
        #pragma unroll
        for (int jp = 0; jp < 2; jp++) {
            float v0, v1;
            unpack2(acc[i][jp], v0, v1);
            int h = h0 + tn + 2 * jp;
            if (r0 < N_SEG) { v0 += b1[h]; v1 += b1[h + 1]; }
            *(float2*)&g_P[(size_t)r * HDIM + h] = make_float2(v0, v1);
        }
    }
}

// ============================================================
// K2: 64 n x 32 s, BK=32, 512 threads, 2x2 scalar microtile  (frozen)
// ============================================================
__global__ __launch_bounds__(512) void fused_k2(
    const float* __restrict__ W2, const float* __restrict__ b2)
{
    __shared__ float As[32][68];
    __shared__ float Bs[32][36];
    __shared__ float w2s[32];
    const int n0 = blockIdx.x * 64;
    const int s0 = blockIdx.y * 32;
    const int t  = threadIdx.x;
    const int tn = (t & 31) * 2;
    const int ts = (t >> 5) * 2;
    const int rr = t >> 3, fq = t & 7;
    const float bb2 = b2[0];

    float acc00 = 0.f, acc01 = 0.f, acc10 = 0.f, acc11 = 0.f;

    float4 areg, breg; float wreg = 0.f;
    areg = *(const float4*)(g_P + (size_t)(n0 + rr) * HDIM + 4 * fq);
    if (t < 256) breg = *(const float4*)(g_P + (size_t)(N_SEG + s0 + rr) * HDIM + 4 * fq);
    if (t < 32)  wreg = W2[t];

    for (int k0 = 0; k0 < HDIM; k0 += 32) {
        __syncthreads();
        {
            int col = rr ^ (4 * fq);
            As[4 * fq + 0][col] = areg.x;
            As[4 * fq + 1][col] = areg.y;
            As[4 * fq + 2][col] = areg.z;
            As[4 * fq + 3][col] = areg.w;
            if (t < 256) {
                Bs[4 * fq + 0][col] = breg.x;
                Bs[4 * fq + 1][col] = breg.y;
                Bs[4 * fq + 2][col] = breg.z;
                Bs[4 * fq + 3][col] = breg.w;
            }
            if (t < 32) w2s[t] = wreg;
        }
        __syncthreads();
        if (k0 + 32 < HDIM) {
            areg = *(const float4*)(g_P + (size_t)(n0 + rr) * HDIM + k0 + 32 + 4 * fq);
            if (t < 256) breg = *(const float4*)(g_P + (size_t)(N_SEG + s0 + rr) * HDIM + k0 + 32 + 4 * fq);
            if (t < 32)  wreg = W2[k0 + 32 + t];
        }
        #pragma unroll
        for (int kk = 0; kk < 32; kk++) {
            int q4 = 4 * (kk >> 2);
            float2 an = *(const float2*)&As[kk][tn ^ q4];
            float2 bv = *(const float2*)&Bs[kk][ts ^ q4];
            float w = w2s[kk];
            acc00 += fmaxf(an.x + bv.x, 0.0f) * w;
            acc01 += fmaxf(an.x + bv.y, 0.0f) * w;
            acc10 += fmaxf(an.y + bv.x, 0.0f) * w;
            acc11 += fmaxf(an.y + bv.y, 0.0f) * w;
        }
    }

    float L[2][2] = {{acc00 + bb2, acc01 + bb2}, {acc10 + bb2, acc11 + bb2}};
    #pragma unroll
    for (int j = 0; j < 2; j++) {
        int s = s0 + ts + j;
        float L0 = L[0][j], L1 = L[1][j];
        *(float2*)&g_logitsT[(size_t)s * N_SEG + n0 + tn] = make_float2(L0, L1);
        float ls0 = fminf(L0, 0.0f) - __logf(1.0f + __expf(-fabsf(L0)));
        float ls1 = fminf(L1, 0.0f) - __logf(1.0f + __expf(-fabsf(L1)));
        *(float2*)&g_logsigT[(size_t)s * N_SEG + n0 + tn] = make_float2(ls0, ls1);
    }
}

// ============================================================
// K3:
//   warp 7  = serial DP with bits inline, distance-2 LDS prefetch
//   warps 0-4 = cp.async loaders, 4-slot ring.
//   Wait protocol: at iteration c, after committing chunk c-2, wait<1>
//   -> chunk c-1 (read NEXT iteration) complete before this barrier.
//   Chunk c (read THIS iteration) was guaranteed one iteration earlier.
// ============================================================
template<bool CLAMP>
__device__ __forceinline__ void dp_chunk(const float* __restrict__ buf, int c, int L,
                                         float& p0, float& p1, float& p2, float& p3,
                                         unsigned* __restrict__ rowbits)
{
    unsigned a0 = 0, a1 = 0, a2 = 0, a3 = 0;
    const int n0 = 4 * L;
    // distance-2 LDS prefetch: chain never waits on shared memory
    float4 lsA = *(const float4*)(buf + 31 * 128 + n0);
    float4 lsB = *(const float4*)(buf + 30 * 128 + n0);
    #pragma unroll
    for (int i = 31; i >= 0; i--) {
        float4 ls = lsA;
        lsA = lsB;
        if (i >= 2) lsB = *(const float4*)(buf + (i - 2) * 128 + n0);
        float nxt3 = __shfl_down_sync(FULLMASK, p0, 1);
        if (L == 31) nxt3 = 0.0f;               // n=127 adds 0
        float c0 = ls.x + p1;
        float c1 = ls.y + p2;
        float c2 = ls.z + p3;
        float c3 = ls.w + nxt3;
        a0 = a0 + a0 + (unsigned)(c0 >= p0);
        a1 = a1 + a1 + (unsigned)(c1 >= p1);
        a2 = a2 + a2 + (unsigned)(c2 >= p2);
        a3 = a3 + a3 + (unsigned)(c3 >= p3);
        float v0 = fmaxf(c0, p0);
        float v1 = fmaxf(c1, p1);
        float v2 = fmaxf(c2, p2);
        float v3 = fmaxf(c3, p3);
        if (CLAMP) {
            int s = c * 32 + i;
            v0 = (s >= n0     && s <= 1920 + n0) ? v0 : NEGV;
            v1 = (s >= n0 + 1 && s <= 1921 + n0) ? v1 : NEGV;
            v2 = (s >= n0 + 2 && s <= 1922 + n0) ? v2 : NEGV;
            v3 = (s >= n0 + 3 && s <= 1923 + n0) ? v3 : NEGV;
        }
        p0 = v0; p1 = v1; p2 = v2; p3 = v3;
    }
    *(uint4*)(rowbits + c * 128 + n0) = make_uint4(a0, a1, a2, a3);
}

// async loader: 160 lanes, 1024 float4s per chunk, fire-and-forget
__device__ __forceinline__ void load_chunk_async(const float* __restrict__ src,
                                                 uint32_t dst_s, int lt)
{
    #pragma unroll
    for (int j = 0; j < 7; j++) {
        int i = lt + 160 * j;
        if (i < 1024) cpa16(dst_s + i * 16, src + i * 4);
    }
    cpa_commit();
}

__global__ __launch_bounds__(256) void dp_k3(float* __restrict__ out, int out_size)
{
    extern __shared__ unsigned char smraw[];
    float*    lsbuf    = (float*)smraw;                      // [4][4096] 64KB ring
    unsigned* rowbits  = (unsigned*)(lsbuf + 4 * 4096);      // [64][128] 32KB
    int*      alignArr = (int*)(rowbits + 64 * 128);         // [128]
    float*    redbuf   = (float*)(alignArr + 128);           // [4]

    const int t = threadIdx.x;
    const int L = t & 31;
    const uint32_t ls_s = smem_u32(lsbuf);

    if (t < 128) alignArr[t] = 0;
    if (t < 160) {
        load_chunk_async(g_logsigT + 63 * 4096, ls_s + (63 & 3) * 16384, t);
        load_chunk_async(g_logsigT + 62 * 4096, ls_s + (62 & 3) * 16384, t);
        cpa_wait<1>();   // chunk 63 complete before the first DP read
    }
    __syncthreads();

    float p0 = NEGV, p1 = NEGV, p2 = NEGV, p3 = NEGV;
    for (int c = 63; c >= 0; c--) {
        if (t >= 224) {
            const float* buf = lsbuf + (c & 3) * 4096;
            if (c >= 4 && c <= 59) dp_chunk<false>(buf, c, L, p0, p1, p2, p3, rowbits);
            else                   dp_chunk<true >(buf, c, L, p0, p1, p2, p3, rowbits);
        } else if (t < 160) {
            if (c >= 2) {
                load_chunk_async(g_logsigT + (size_t)(c - 2) * 4096,
                                 ls_s + ((c - 2) & 3) * 16384, t);
                cpa_wait<1>();   // newest pending = chunk c-2; chunk c-1 done
            } else if (c == 1) {
                cpa_wait<0>();   // chunk 0 done before final iteration
            }
        }
        __syncthreads();
    }

    // walk: first set take-bit at s >= scur per n (equivalent to ref scan)
    if (t == 0) {
        int scur = 0;
        for (int n = 0; n < 128; n++) {
            int wdi = scur >> 5;
            unsigned word = rowbits[wdi * 128 + n] & (0xFFFFFFFFu << (scur & 31));
            while (word == 0) {
                wdi++;
                if (wdi >= 64) break;
                word = rowbits[wdi * 128 + n];
            }
            if (wdi >= 64) break;
            int s = wdi * 32 + (__ffs(word) - 1);
            alignArr[n] = s;
            scur = s + 1;
            if (scur >= S_VID) break;
        }
    }
    __syncthreads();

    // outputs
    if (t < 128) {
        int a = alignArr[t];
        out[(size_t)(S_VID + t) * RTOT + a] = 1.0f;
        float v = g_logitsT[(size_t)a * N_SEG + t];
        #pragma unroll
        for (int o = 16; o; o >>= 1) v += __shfl_down_sync(FULLMASK, v, o);
        if ((t & 31) == 0) redbuf[t >> 5] = v;
    }
    __syncthreads();
    if (t == 0) {
        float sum = redbuf[0] + redbuf[1] + redbuf[2] + redbuf[3];
        if (out_size > RTOT * RTOT) out[(size_t)RTOT * RTOT] = sum * (1.0f / 128.0f);
    }
}

// ============================================================
extern "C" void kernel_launch(void* const* d_in, const int* in_sizes, int n_in,
                              void* d_out, int out_size)
{
    const float* seg = (const float*)d_in[0];
    const float* vid = (const float*)d_in[1];
    const float* W1  = (const float*)d_in[2];
    const float* b1  = (const float*)d_in[3];
    const float* W2  = (const float*)d_in[4];
    const float* b2  = (const float*)d_in[5];
    float* out = (float*)d_out;

    cudaMemsetAsync(out, 0, (size_t)out_size * sizeof(float), 0);  // ~2 launches
    dummy_k<<<1, 32>>>();
    gemm_k1<<<dim3(34, 4), 512>>>(seg, vid, W1, b1);
    fused_k2<<<dim3(2, 64), 512>>>(W2, b2);

    const int smem_k3 = 4 * 4096 * 4 + 64 * 128 * 4 + 128 * 4 + 4 * 4;
    cudaFuncSetAttribute(dp_k3, cudaFuncAttributeMaxDynamicSharedMemorySize, smem_k3);
    dp_k3<<<1, 256, smem_k3>>>(out, out_size);
}